// round 13
// baseline (speedup 1.0000x reference)
#include <cuda_runtime.h>
#include <cuda_fp16.h>
#include <cstdint>

#define BB 128
#define HH 1024
#define LL 256
#define NN 64

// Scratch (device globals: no allocations allowed)
__device__ float  g_k[HH * LL];                       // 1 MB  : S4D conv kernel (H,L) fp32
__device__ __half g_Wh[2 * HH * HH];                  // 4 MB  : W_out fp16
__device__ __half g_xh[(size_t)BB * HH * LL];         // 64 MB : x in fp16 [b][h][l]
__device__ __half g_yh[(size_t)BB * HH * LL];         // 64 MB : post-gelu activations fp16 [b][h][l]
__device__ __half g_T[(size_t)HH * LL * LL];          // 134 MB: T[h][s][l] = k_h[l-s] + (s==l)*D_h

// ---------------------------------------------------------------------------
// helpers
// ---------------------------------------------------------------------------
__device__ __forceinline__ float gelu_tanh(float v) {
    float t = tanhf(0.7978845608028654f * (v + 0.044715f * v * v * v));
    return 0.5f * v * (1.0f + t);
}
__device__ __forceinline__ uint32_t smem_u32(const void* p) {
    return (uint32_t)__cvta_generic_to_shared(p);
}
__device__ __forceinline__ void cp_async16(uint32_t dst, const void* src) {
    asm volatile("cp.async.cg.shared.global [%0], [%1], 16;\n" :: "r"(dst), "l"(src));
}
__device__ __forceinline__ void cp_commit() { asm volatile("cp.async.commit_group;\n"); }
__device__ __forceinline__ void cp_wait0() { asm volatile("cp.async.wait_group 0;\n"); }
__device__ __forceinline__ void cp_wait1() { asm volatile("cp.async.wait_group 1;\n"); }

__device__ __forceinline__ void mma_f16(float c[4], const uint32_t a[4],
                                        uint32_t b0, uint32_t b1) {
    asm volatile(
        "mma.sync.aligned.m16n8k16.row.col.f32.f16.f16.f32 "
        "{%0,%1,%2,%3}, {%4,%5,%6,%7}, {%8,%9}, {%0,%1,%2,%3};"
        : "+f"(c[0]), "+f"(c[1]), "+f"(c[2]), "+f"(c[3])
        : "r"(a[0]), "r"(a[1]), "r"(a[2]), "r"(a[3]), "r"(b0), "r"(b1));
}

#define LDM_X4(r0, r1, r2, r3, addr) \
    asm volatile("ldmatrix.sync.aligned.m8n8.x4.shared.b16 {%0,%1,%2,%3}, [%4];" \
                 : "=r"(r0), "=r"(r1), "=r"(r2), "=r"(r3) : "r"(addr))
#define LDM_X4T(r0, r1, r2, r3, addr) \
    asm volatile("ldmatrix.sync.aligned.m8n8.x4.trans.shared.b16 {%0,%1,%2,%3}, [%4];" \
                 : "=r"(r0), "=r"(r1), "=r"(r2), "=r"(r3) : "r"(addr))

// ---------------------------------------------------------------------------
// Kernel 1: S4D kernel materialization (fp32 k)
// ---------------------------------------------------------------------------
__global__ __launch_bounds__(256) void k_kernel(
    const float* __restrict__ log_dt, const float* __restrict__ A_real_log,
    const float* __restrict__ A_imag, const float* __restrict__ C_re,
    const float* __restrict__ C_im) {
    int h = blockIdx.x;
    __shared__ float sCr[NN], sCi[NN], sAr[NN], sAi[NN];
    int tid = threadIdx.x;
    if (tid < NN) {
        float dt = expf(log_dt[h]);
        float Ar = -expf(A_real_log[h * NN + tid]);
        float Ai = A_imag[h * NN + tid];
        float dAr = Ar * dt, dAi = Ai * dt;
        float er = expf(dAr), sv, cv;
        sincosf(dAi, &sv, &cv);
        float Exr = er * cv - 1.0f;
        float Exi = er * sv;
        float cr = C_re[h * NN + tid], ci = C_im[h * NN + tid];
        float nr = cr * Exr - ci * Exi;
        float ni = cr * Exi + ci * Exr;
        float den = 1.0f / (Ar * Ar + Ai * Ai);
        sCr[tid] = (nr * Ar + ni * Ai) * den;
        sCi[tid] = (ni * Ar - nr * Ai) * den;
        sAr[tid] = dAr;
        sAi[tid] = dAi;
    }
    __syncthreads();
    float l = (float)tid;
    float acc = 0.0f;
#pragma unroll 4
    for (int n = 0; n < NN; n++) {
        float mag = expf(sAr[n] * l);
        float sv, cv;
        sincosf(sAi[n] * l, &sv, &cv);
        acc += sCr[n] * (mag * cv) - sCi[n] * (mag * sv);
    }
    g_k[h * LL + tid] = 2.0f * acc;
}

// ---------------------------------------------------------------------------
// Kernel 2: fp16-cast W (row-major)
// ---------------------------------------------------------------------------
__global__ __launch_bounds__(256) void wprep_kernel(const float* __restrict__ W) {
    int i = (blockIdx.x * 256 + threadIdx.x) * 4;
    if (i >= 2 * HH * HH) return;
    float4 v = *(const float4*)&W[i];
    union { __half2 h[2]; uint2 u; } c;
    c.h[0] = __floats2half2_rn(v.x, v.y);
    c.h[1] = __floats2half2_rn(v.z, v.w);
    *(uint2*)&g_Wh[i] = c.u;
}

// ---------------------------------------------------------------------------
// Kernel 2b: fp16-cast x
// ---------------------------------------------------------------------------
__global__ __launch_bounds__(256) void xprep_kernel(const float* __restrict__ x) {
    size_t i = ((size_t)blockIdx.x * 256 + threadIdx.x) * 4;
    float4 v = *(const float4*)&x[i];
    union { __half2 h[2]; uint2 u; } c;
    c.h[0] = __floats2half2_rn(v.x, v.y);
    c.h[1] = __floats2half2_rn(v.z, v.w);
    *(uint2*)&g_xh[i] = c.u;
}

// ---------------------------------------------------------------------------
// Kernel 2c: Toeplitz materialization with D folded into the diagonal:
// T[h][s][l] = k_h[l-s] (l>s), k_h[0]+D_h (l==s), 0 (l<s).
// One block per head; coalesced 16B stores.
// ---------------------------------------------------------------------------
__global__ __launch_bounds__(256) void tprep_kernel(const float* __restrict__ D) {
    __shared__ float kf[256];
    int h = blockIdx.x;
    int tid = threadIdx.x;
    kf[tid] = g_k[(size_t)h * LL + tid];
    __syncthreads();
    float Dv = D[h];
    __half* Th = g_T + (size_t)h * LL * LL;
#pragma unroll 4
    for (int idx = tid; idx < 256 * 32; idx += 256) {
        int s = idx >> 5;
        int l0 = (idx & 31) * 8;
        union { __half hv[8]; uint4 u; } pk;
#pragma unroll
        for (int j = 0; j < 8; j++) {
            int l = l0 + j;
            float v = (l > s) ? kf[l - s] : ((l == s) ? (kf[0] + Dv) : 0.0f);
            pk.hv[j] = __float2half(v);
        }
        *(uint4*)&Th[(size_t)s * LL + l0] = pk.u;
    }
}

// ---------------------------------------------------------------------------
// Kernel 3: conv as per-head Toeplitz GEMM (tensor cores), T from gmem,
// D-skip already folded into T's diagonal -> epilogue is gelu+store only.
// Y[b][l] = sum_s X[b][s] * T[s][l]
// Block = (mb in 0..1, head h): M=64 batches, N=256 l, K=256 s in 8 k32 chunks.
// 8 warps = 2(m) x 4(n); warp tile m32 x n64. Double-buffered cp.async.
// Causal skip: warp wn computes chunk k0 only if wn*64+63 >= k0.
// mma rows are BATCHES (stride HH*LL in [b][h][l]); m16 sub-tiles at +0/+16.
// ---------------------------------------------------------------------------
#define XP 40          // X tile pitch (halfs): 32 k + 8 pad
#define TP 264         // T tile pitch (halfs): 256 l + 8 pad

__global__ __launch_bounds__(256) void convgemm_kernel() {
    __shared__ __align__(16) __half Xs[2][64 * XP];     // 10240 B
    __shared__ __align__(16) __half Ts[2][32 * TP];     // 33792 B

    int mb = blockIdx.x;            // 0..1 (64 batches each)
    int h  = blockIdx.y;
    int tid = threadIdx.x;
    int lane = tid & 31;
    int wid = tid >> 5;
    int wm = wid & 1;               // m: 32 rows
    int wn = wid >> 1;              // n: 64 cols

    float acc[2][8][4];
#pragma unroll
    for (int mi = 0; mi < 2; mi++)
#pragma unroll
        for (int t = 0; t < 8; t++)
#pragma unroll
            for (int r = 0; r < 4; r++) acc[mi][t][r] = 0.0f;

    // X staging: row = tid>>2 (0..63), seg = (tid&3)*8 halfs; 1 cp.async each
    int xr = tid >> 2, xseg = (tid & 3) * 8;
    const __half* xS = g_xh + ((size_t)(mb * 64 + xr) * HH + h) * LL + xseg;  // += 32/chunk
    uint32_t xD[2] = { smem_u32(&Xs[0][xr * XP + xseg]),
                       smem_u32(&Xs[1][xr * XP + xseg]) };

    // T staging: row = tid>>3 (0..31), seg = (tid&7)*32 halfs; 4 cp.async each
    int trow = tid >> 3, tseg = (tid & 7) * 32;
    const __half* tS = g_T + (size_t)h * LL * LL + (size_t)trow * LL + tseg;  // += 32*LL/chunk
    uint32_t tD[2] = { smem_u32(&Ts[0][trow * TP + tseg]),
                       smem_u32(&Ts[1][trow * TP + tseg]) };

    // fragment addresses
    int lm = lane & 15, lh = lane >> 4;
    uint32_t xAddr[2] = { smem_u32(&Xs[0][(wm * 32 + lm) * XP + lh * 8]),
                          smem_u32(&Xs[1][(wm * 32 + lm) * XP + lh * 8]) };
    uint32_t tAddr[2] = { smem_u32(&Ts[0][lm * TP + wn * 64 + lh * 8]),
                          smem_u32(&Ts[1][lm * TP + wn * 64 + lh * 8]) };

#define STAGE_CONV(buf) do { \
        cp_async16(xD[buf], xS); \
        cp_async16(tD[buf], tS);      cp_async16(tD[buf] + 16, tS + 8); \
        cp_async16(tD[buf] + 32, tS + 16); cp_async16(tD[buf] + 48, tS + 24); \
        cp_commit(); xS += 32; tS += 32 * LL; } while (0)

#define CONV_COMPUTE(buf, k0) do { \
        if (wn * 64 + 63 >= (k0)) { \
            _Pragma("unroll") \
            for (int s = 0; s < 2; s++) { \
                uint32_t aa0[4], aa1[4]; \
                LDM_X4(aa0[0], aa0[1], aa0[2], aa0[3], xAddr[buf] + s * 32); \
                LDM_X4(aa1[0], aa1[1], aa1[2], aa1[3], xAddr[buf] + s * 32 + 16 * XP * 2); \
                _Pragma("unroll") \
                for (int p = 0; p < 4; p++) { \
                    if (wn * 64 + p * 16 + 15 >= (k0)) { \
                        uint32_t b0, b1, b2, b3; \
                        LDM_X4T(b0, b1, b2, b3, tAddr[buf] + s * (16 * TP * 2) + p * 32); \
                        mma_f16(acc[0][2 * p],     aa0, b0, b1); \
                        mma_f16(acc[0][2 * p + 1], aa0, b2, b3); \
                        mma_f16(acc[1][2 * p],     aa1, b0, b1); \
                        mma_f16(acc[1][2 * p + 1], aa1, b2, b3); \
                    } \
                } \
            } \
        } } while (0)

    // prologue
    STAGE_CONV(0);
    cp_wait0();
    __syncthreads();

#pragma unroll 1
    for (int c = 0; c < 8; c++) {
        int cur = c & 1, nxt = cur ^ 1;
        if (c < 7) STAGE_CONV(nxt);
        CONV_COMPUTE(cur, c * 32);
        if (c < 7) cp_wait0();
        __syncthreads();
    }

    // epilogue: gelu + fp16 store (D already in T). batch stride = HH*LL.
    int r = lane >> 2;
    int c2 = (lane & 3) << 1;
    const size_t BSTRIDE8 = (size_t)8 * HH * LL;
#pragma unroll
    for (int mi = 0; mi < 2; mi++) {
        int row0 = mb * 64 + wm * 32 + mi * 16 + r;      // batch index
#pragma unroll
        for (int t = 0; t < 8; t++) {
            int l = wn * 64 + t * 8 + c2;
            size_t a0 = ((size_t)row0 * HH + h) * LL + l;
            size_t a8 = a0 + BSTRIDE8;                   // batch row0+8
            float y0 = gelu_tanh(acc[mi][t][0]);
            float y1 = gelu_tanh(acc[mi][t][1]);
            float y2 = gelu_tanh(acc[mi][t][2]);
            float y3 = gelu_tanh(acc[mi][t][3]);
            *(__half2*)&g_yh[a0] = __floats2half2_rn(y0, y1);
            *(__half2*)&g_yh[a8] = __floats2half2_rn(y2, y3);
        }
    }
}

// ---------------------------------------------------------------------------
// Kernel 4: fp16 GEMM + GLU, k64 chunks (64 HMMA/warp per barrier),
// 3-stage cp.async pipeline, wait_group 1, one barrier per chunk.
// Block: 64 h-out (both GLU halves) x 128 l; 8 warps = 4(m) x 2(n).
// ---------------------------------------------------------------------------
#define AP 72                          // 64 k + 8 pad
#define BP 136                         // 128 l + 8 pad
#define A_H (128 * AP)                 // 9216 halfs
#define B_H (64 * BP)                  // 8704 halfs
#define ST_H (A_H + B_H)               // 17920 halfs
#define ST_B (ST_H * 2)                // 35840 B / stage
#define GEMM_SMEM_BYTES (3 * ST_B)     // 107520 B

__global__ __launch_bounds__(256, 2) void gemm_glu_kernel(const float* __restrict__ bias,
                                                          float* __restrict__ out) {
    extern __shared__ __half smh[];

    int lblk = blockIdx.x;
    int hb   = blockIdx.y;
    int b    = blockIdx.z;
    int tid = threadIdx.x;
    int lane = tid & 31;
    int wid = tid >> 5;
    int wm = wid & 3;
    int wn = wid >> 2;

    float ca[8][4], cb[8][4];
#pragma unroll
    for (int t = 0; t < 8; t++)
#pragma unroll
        for (int r = 0; r < 4; r++) { ca[t][r] = 0.0f; cb[t][r] = 0.0f; }

    // A staging: row = tid>>1 (0..127), seg = (tid&1)*32 halfs; 4 cp.async
    int arow = tid >> 1, aseg = (tid & 1) * 32;
    int wrow = (arow < 64) ? (hb * 64 + arow) : (960 + hb * 64 + arow);
    const __half* aS = g_Wh + (size_t)wrow * HH + aseg;                 // += 64/chunk
    uint32_t aD = smem_u32(smh + arow * AP + aseg);

    // B staging: row = tid>>2 (0..63), seg = (tid&3)*32 halfs; 4 cp.async
    int brow = tid >> 2, bseg = (tid & 3) * 32;
    const __half* bS = g_yh + (size_t)b * HH * LL + (size_t)brow * LL + lblk * 128 + bseg;
    uint32_t bD = smem_u32(smh + A_H + brow * BP + bseg);

#define STAGE(off) do { \
        cp_async16(aD + (off), aS);      cp_async16(aD + (off) + 16, aS + 8); \
        cp_async16(aD + (off) + 32, aS + 16); cp_async16(aD + (off) + 48, aS + 24); \
        cp_async16(bD + (off), bS);      cp_async16(bD + (off) + 16, bS + 8); \
        cp_async16(bD + (off) + 32, bS + 16); cp_async16(bD + (off) + 48, bS + 24); \
        cp_commit(); aS += 64; bS += 64 * LL; } while (0)

    int lm = lane & 15, lh = lane >> 4;
    uint32_t aAddrA = smem_u32(smh + (wm * 16 + lm) * AP + lh * 8);
    uint32_t aAddrB = aAddrA + 64 * AP * 2;
    uint32_t bAddr  = smem_u32(smh + A_H + lm * BP + wn * 64 + lh * 8);

#define COMPUTE(off) do { \
        _Pragma("unroll") \
        for (int s = 0; s < 4; s++) { \
            uint32_t aa[4], ab[4]; \
            LDM_X4(aa[0], aa[1], aa[2], aa[3], aAddrA + (off) + s * 32); \
            LDM_X4(ab[0], ab[1], ab[2], ab[3], aAddrB + (off) + s * 32); \
            _Pragma("unroll") \
            for (int p = 0; p < 4; p++) { \
                uint32_t b0, b1, b2, b3; \
                LDM_X4T(b0, b1, b2, b3, bAddr + (off) + s * (16 * BP * 2) + p * 32); \
                mma_f16(ca[2 * p],     aa, b0, b1); \
                mma_f16(ca[2 * p + 1], aa, b2, b3); \
                mma_f16(cb[2 * p],     ab, b0, b1); \
                mma_f16(cb[2 * p + 1], ab, b2, b3); \
            } \
        } } while (0)

    // 3-stage pipeline over 16 k64 chunks
    STAGE(0);
    STAGE(ST_B);
    uint32_t offC = 0, offS = 2 * ST_B;

#pragma unroll 1
    for (int i = 0; i < 16; i++) {
        if (i < 15) cp_wait1(); else cp_wait0();
        __syncthreads();
        if (i < 14) STAGE(offS);
        COMPUTE(offC);
        offC += ST_B; if (offC == 3 * ST_B) offC = 0;
        offS += ST_B; if (offS == 3 * ST_B) offS = 0;
    }

    // epilogue: bias + GLU
    int r = lane >> 2;
    int c2 = (lane & 3) << 1;
    int h = hb * 64 + wm * 16 + r;
    float ba0 = bias[h],     bb0 = bias[h + HH];
    float ba8 = bias[h + 8], bb8 = bias[h + 8 + HH];
    size_t ob0 = ((size_t)b * HH + h) * LL;
    size_t ob8 = ob0 + (size_t)8 * LL;
#pragma unroll
    for (int t = 0; t < 8; t++) {
        int ll = lblk * 128 + wn * 64 + t * 8 + c2;
        float av, bv;
        float2 w0, w8;
        av = ca[t][0] + ba0; bv = cb[t][0] + bb0;
        w0.x = av * (1.0f / (1.0f + expf(-bv)));
        av = ca[t][1] + ba0; bv = cb[t][1] + bb0;
        w0.y = av * (1.0f / (1.0f + expf(-bv)));
        av = ca[t][2] + ba8; bv = cb[t][2] + bb8;
        w8.x = av * (1.0f / (1.0f + expf(-bv)));
        av = ca[t][3] + ba8; bv = cb[t][3] + bb8;
        w8.y = av * (1.0f / (1.0f + expf(-bv)));
        *(float2*)&out[ob0 + ll] = w0;
        *(float2*)&out[ob8 + ll] = w8;
    }
}

// ---------------------------------------------------------------------------
extern "C" void kernel_launch(void* const* d_in, const int* in_sizes, int n_in,
                              void* d_out, int out_size) {
    const float* x          = (const float*)d_in[0];
    const float* log_dt     = (const float*)d_in[1];
    const float* A_real_log = (const float*)d_in[2];
    const float* A_imag     = (const float*)d_in[3];
    const float* C_re       = (const float*)d_in[4];
    const float* C_im       = (const float*)d_in[5];
    const float* D          = (const float*)d_in[6];
    const float* W_out      = (const float*)d_in[7];
    const float* b_out      = (const float*)d_in[8];
    float* out = (float*)d_out;

    cudaFuncSetAttribute(gemm_glu_kernel, cudaFuncAttributeMaxDynamicSharedMemorySize,
                         GEMM_SMEM_BYTES);

    k_kernel<<<HH, 256>>>(log_dt, A_real_log, A_imag, C_re, C_im);
    wprep_kernel<<<(2 * HH * HH) / 1024, 256>>>(W_out);
    xprep_kernel<<<(int)(((size_t)BB * HH * LL) / 1024), 256>>>(x);
    tprep_kernel<<<HH, 256>>>(D);
    convgemm_kernel<<<dim3(2, HH), 256>>>();
    gemm_glu_kernel<<<dim3(2, 16, BB), 256, GEMM_SMEM_BYTES>>>(b_out, out);
}

// round 15
// speedup vs baseline: 1.1592x; 1.1592x over previous
#include <cuda_runtime.h>
#include <cuda_fp16.h>
#include <cstdint>

#define BB 128
#define HH 1024
#define LL 256
#define NN 64

// Scratch (device globals: no allocations allowed)
__device__ float  g_k[HH * LL];                       // 1 MB : S4D conv kernel (H,L) fp32
__device__ __half g_Wh[2 * HH * HH];                  // 4 MB : W_out fp16
__device__ __half g_yh[(size_t)BB * HH * LL];         // 64 MB: post-gelu activations fp16 [b][h][l]

// ---------------------------------------------------------------------------
// helpers
// ---------------------------------------------------------------------------
__device__ __forceinline__ float gelu_tanh(float v) {
    float t = tanhf(0.7978845608028654f * (v + 0.044715f * v * v * v));
    return 0.5f * v * (1.0f + t);
}
__device__ __forceinline__ uint32_t smem_u32(const void* p) {
    return (uint32_t)__cvta_generic_to_shared(p);
}
__device__ __forceinline__ void cp_async16(uint32_t dst, const void* src) {
    asm volatile("cp.async.cg.shared.global [%0], [%1], 16;\n" :: "r"(dst), "l"(src));
}
__device__ __forceinline__ void cp_commit() { asm volatile("cp.async.commit_group;\n"); }
__device__ __forceinline__ void cp_wait0() { asm volatile("cp.async.wait_group 0;\n"); }
__device__ __forceinline__ void cp_wait1() { asm volatile("cp.async.wait_group 1;\n"); }

__device__ __forceinline__ void mma_f16(float c[4], const uint32_t a[4],
                                        uint32_t b0, uint32_t b1) {
    asm volatile(
        "mma.sync.aligned.m16n8k16.row.col.f32.f16.f16.f32 "
        "{%0,%1,%2,%3}, {%4,%5,%6,%7}, {%8,%9}, {%0,%1,%2,%3};"
        : "+f"(c[0]), "+f"(c[1]), "+f"(c[2]), "+f"(c[3])
        : "r"(a[0]), "r"(a[1]), "r"(a[2]), "r"(a[3]), "r"(b0), "r"(b1));
}

#define LDM_X4(r0, r1, r2, r3, addr) \
    asm volatile("ldmatrix.sync.aligned.m8n8.x4.shared.b16 {%0,%1,%2,%3}, [%4];" \
                 : "=r"(r0), "=r"(r1), "=r"(r2), "=r"(r3) : "r"(addr))
#define LDM_X4T(r0, r1, r2, r3, addr) \
    asm volatile("ldmatrix.sync.aligned.m8n8.x4.trans.shared.b16 {%0,%1,%2,%3}, [%4];" \
                 : "=r"(r0), "=r"(r1), "=r"(r2), "=r"(r3) : "r"(addr))

// ---------------------------------------------------------------------------
// Kernel 1: S4D kernel materialization (fp32 k)
// ---------------------------------------------------------------------------
__global__ __launch_bounds__(256) void k_kernel(
    const float* __restrict__ log_dt, const float* __restrict__ A_real_log,
    const float* __restrict__ A_imag, const float* __restrict__ C_re,
    const float* __restrict__ C_im) {
    int h = blockIdx.x;
    __shared__ float sCr[NN], sCi[NN], sAr[NN], sAi[NN];
    int tid = threadIdx.x;
    if (tid < NN) {
        float dt = expf(log_dt[h]);
        float Ar = -expf(A_real_log[h * NN + tid]);
        float Ai = A_imag[h * NN + tid];
        float dAr = Ar * dt, dAi = Ai * dt;
        float er = expf(dAr), sv, cv;
        sincosf(dAi, &sv, &cv);
        float Exr = er * cv - 1.0f;
        float Exi = er * sv;
        float cr = C_re[h * NN + tid], ci = C_im[h * NN + tid];
        float nr = cr * Exr - ci * Exi;
        float ni = cr * Exi + ci * Exr;
        float den = 1.0f / (Ar * Ar + Ai * Ai);
        sCr[tid] = (nr * Ar + ni * Ai) * den;
        sCi[tid] = (ni * Ar - nr * Ai) * den;
        sAr[tid] = dAr;
        sAi[tid] = dAi;
    }
    __syncthreads();
    float l = (float)tid;
    float acc = 0.0f;
#pragma unroll 4
    for (int n = 0; n < NN; n++) {
        float mag = expf(sAr[n] * l);
        float sv, cv;
        sincosf(sAi[n] * l, &sv, &cv);
        acc += sCr[n] * (mag * cv) - sCi[n] * (mag * sv);
    }
    g_k[h * LL + tid] = 2.0f * acc;
}

// ---------------------------------------------------------------------------
// Kernel 2: fp16-cast W (row-major)
// ---------------------------------------------------------------------------
__global__ __launch_bounds__(256) void wprep_kernel(const float* __restrict__ W) {
    int i = (blockIdx.x * 256 + threadIdx.x) * 4;
    if (i >= 2 * HH * HH) return;
    float4 v = *(const float4*)&W[i];
    union { __half2 h[2]; uint2 u; } c;
    c.h[0] = __floats2half2_rn(v.x, v.y);
    c.h[1] = __floats2half2_rn(v.z, v.w);
    *(uint2*)&g_Wh[i] = c.u;
}

// ---------------------------------------------------------------------------
// Kernel 3: conv as per-head Toeplitz GEMM (tensor cores), R10 structure.
// Y[b][l] = sum_s X[b][s] * T[s][l],  T[s][l] = k_h[l-s] (l>=s else 0)
// Block = (mb in 0..1, head h): M=64 batches, N=256 l, K=256 s in 16 chunks.
// 8 warps = 2(m) x 4(n); warp tile m32 x n64.
// T generated on the fly (double-buffered). X staged directly from fp32 x:
// LDG.128 prefetch -> cvt -> STS after compute (xprep kernel eliminated).
// Causal skip: warp wn computes chunk k0 only if wn*64+63 >= k0.
// Epilogue: + D*x (fp32 read), gelu, fp16 store. mma rows are BATCHES
// (stride HH*LL); m16 sub-tiles at row offsets +0/+16.
// ---------------------------------------------------------------------------
#define XP 24          // X tile pitch (halfs)
#define TP 264         // T tile pitch (halfs)

__global__ __launch_bounds__(256) void convgemm_kernel(const float* __restrict__ x,
                                                       const float* __restrict__ D) {
    __shared__ __half kh[256];
    __shared__ __align__(16) __half Xs[2][64 * XP];     // 6144 B
    __shared__ __align__(16) __half Ts[2][16 * TP];     // 16896 B

    int mb = blockIdx.x;            // 0..1 (64 batches each)
    int h  = blockIdx.y;
    int tid = threadIdx.x;
    int lane = tid & 31;
    int wid = tid >> 5;
    int wm = wid & 1;               // m: 32 rows
    int wn = wid >> 1;              // n: 64 cols

    // kernel row -> fp16 smem
    kh[tid] = __float2half(g_k[(size_t)h * LL + tid]);

    float acc[2][8][4];
#pragma unroll
    for (int mi = 0; mi < 2; mi++)
#pragma unroll
        for (int t = 0; t < 8; t++)
#pragma unroll
            for (int r = 0; r < 4; r++) acc[mi][t][r] = 0.0f;

    // X staging: threads 0..127 -> (row xr, 8-half segment xseg), from fp32 x
    int xr = tid >> 1, xseg = (tid & 1) * 8;
    const float* xF = x + ((size_t)(mb * 64 + xr) * HH + h) * LL + xseg;   // += 16/chunk
    __half* xDst[2] = { &Xs[0][xr * XP + xseg], &Xs[1][xr * XP + xseg] };

    // T generation mapping: si = tid>>4 (s within chunk), l0 = (tid&15)*16
    int si = tid >> 4;
    int l0g = (tid & 15) * 16;

    // fragment addresses
    int lm = lane & 15, lh = lane >> 4;
    uint32_t xAddr[2] = { smem_u32(&Xs[0][(wm * 32 + lm) * XP + lh * 8]),
                          smem_u32(&Xs[1][(wm * 32 + lm) * XP + lh * 8]) };
    uint32_t tAddr[2] = { smem_u32(&Ts[0][lm * TP + wn * 64 + lh * 8]),
                          smem_u32(&Ts[1][lm * TP + wn * 64 + lh * 8]) };

#define GEN_T(buf, k0) do { \
        int sg = (k0) + si; \
        int lbase = (k0) & ~63; \
        if (l0g + 15 >= lbase) { \
            _Pragma("unroll") \
            for (int j = 0; j < 8; j++) { \
                int l = l0g + 2 * j; \
                __half v0 = (l >= sg)     ? kh[l - sg]     : __half(0.0f); \
                __half v1 = (l + 1 >= sg) ? kh[l + 1 - sg] : __half(0.0f); \
                *(__half2*)&Ts[buf][si * TP + l] = __halves2half2(v0, v1); \
            } \
        } } while (0)

#define LOAD_X_REGS(v0, v1) do { \
        if (tid < 128) { v0 = *(const float4*)xF; v1 = *(const float4*)(xF + 4); xF += 16; } \
        } while (0)

#define STS_X(buf, v0, v1) do { \
        if (tid < 128) { \
            union { __half hv[8]; uint4 u; } cvt; \
            *(__half2*)&cvt.hv[0] = __floats2half2_rn(v0.x, v0.y); \
            *(__half2*)&cvt.hv[2] = __floats2half2_rn(v0.z, v0.w); \
            *(__half2*)&cvt.hv[4] = __floats2half2_rn(v1.x, v1.y); \
            *(__half2*)&cvt.hv[6] = __floats2half2_rn(v1.z, v1.w); \
            *(uint4*)xDst[buf] = cvt.u; \
        } } while (0)

#define CONV_COMPUTE(buf, k0) do { \
        if (wn * 64 + 63 >= (k0)) { \
            uint32_t aa0[4], aa1[4]; \
            LDM_X4(aa0[0], aa0[1], aa0[2], aa0[3], xAddr[buf]); \
            LDM_X4(aa1[0], aa1[1], aa1[2], aa1[3], xAddr[buf] + 16 * XP * 2); \
            _Pragma("unroll") \
            for (int p = 0; p < 4; p++) { \
                if (wn * 64 + p * 16 + 15 >= (k0)) { \
                    uint32_t b0, b1, b2, b3; \
                    LDM_X4T(b0, b1, b2, b3, tAddr[buf] + p * 32); \
                    mma_f16(acc[0][2 * p],     aa0, b0, b1); \
                    mma_f16(acc[0][2 * p + 1], aa0, b2, b3); \
                    mma_f16(acc[1][2 * p],     aa1, b0, b1); \
                    mma_f16(acc[1][2 * p + 1], aa1, b2, b3); \
                } \
            } \
        } } while (0)

    // prologue: chunk 0 -> buf0 (barrier first: GEN_T reads kh written above)
    __syncthreads();
    {
        float4 v0, v1;
        LOAD_X_REGS(v0, v1);
        GEN_T(0, 0);
        STS_X(0, v0, v1);
    }
    __syncthreads();

#pragma unroll 1
    for (int c = 0; c < 16; c++) {
        int cur = c & 1, nxt = cur ^ 1;
        float4 v0, v1;
        if (c < 15) {
            LOAD_X_REGS(v0, v1);        // LDG latency overlaps GEN_T + compute
            GEN_T(nxt, (c + 1) * 16);
        }
        CONV_COMPUTE(cur, c * 16);
        if (c < 15) STS_X(nxt, v0, v1);
        __syncthreads();
    }

    // epilogue: + D*x (fp32), gelu, store fp16. batch stride = HH*LL!
    float Dv = D[h];
    int r = lane >> 2;
    int c2 = (lane & 3) << 1;
    const size_t BSTRIDE8 = (size_t)8 * HH * LL;
#pragma unroll
    for (int mi = 0; mi < 2; mi++) {
        int row0 = mb * 64 + wm * 32 + mi * 16 + r;      // batch index
#pragma unroll
        for (int t = 0; t < 8; t++) {
            int l = wn * 64 + t * 8 + c2;
            size_t a0 = ((size_t)row0 * HH + h) * LL + l;
            size_t a8 = a0 + BSTRIDE8;                   // batch row0+8
            float2 x0 = *(const float2*)&x[a0];
            float2 x8 = *(const float2*)&x[a8];
            float y0 = gelu_tanh(acc[mi][t][0] + Dv * x0.x);
            float y1 = gelu_tanh(acc[mi][t][1] + Dv * x0.y);
            float y2 = gelu_tanh(acc[mi][t][2] + Dv * x8.x);
            float y3 = gelu_tanh(acc[mi][t][3] + Dv * x8.y);
            *(__half2*)&g_yh[a0] = __floats2half2_rn(y0, y1);
            *(__half2*)&g_yh[a8] = __floats2half2_rn(y2, y3);
        }
    }
}

// ---------------------------------------------------------------------------
// Kernel 4: fp16 GEMM + GLU (mma.sync m16n8k16 + ldmatrix), 3-stage cp.async
// pipeline with wait_group 1 (one barrier per k32 chunk). R10-proven.
// Block: 64 h-out (both GLU halves) x 128 l; 8 warps = 4(m) x 2(n).
// ---------------------------------------------------------------------------
#define AP 40
#define BP 136
#define A_H (128 * AP)                 // 5120 halfs
#define B_H (32 * BP)                  // 4352 halfs
#define ST_H (A_H + B_H)               // 9472 halfs
#define ST_B (ST_H * 2)                // 18944 B / stage
#define GEMM_SMEM_BYTES (3 * ST_B)     // 56832 B

__global__ __launch_bounds__(256, 2) void gemm_glu_kernel(const float* __restrict__ bias,
                                                          float* __restrict__ out) {
    extern __shared__ __half smh[];

    int lblk = blockIdx.x;
    int hb   = blockIdx.y;
    int b    = blockIdx.z;
    int tid = threadIdx.x;
    int lane = tid & 31;
    int wid = tid >> 5;
    int wm = wid & 3;
    int wn = wid >> 2;

    float ca[8][4], cb[8][4];
#pragma unroll
    for (int t = 0; t < 8; t++)
#pragma unroll
        for (int r = 0; r < 4; r++) { ca[t][r] = 0.0f; cb[t][r] = 0.0f; }

    // staging descriptors
    int arow = tid >> 1, aseg2 = (tid & 1) * 2;
    int wrow = (arow < 64) ? (hb * 64 + arow) : (960 + hb * 64 + arow);
    const __half* aS = g_Wh + (size_t)wrow * HH + aseg2 * 8;
    uint32_t aD = smem_u32(smh + arow * AP + aseg2 * 8);

    int brow = tid >> 3, bs2 = (tid & 7) * 2;
    const __half* bS = g_yh + (size_t)b * HH * LL + (size_t)brow * LL + lblk * 128 + bs2 * 8;
    uint32_t bD = smem_u32(smh + A_H + brow * BP + bs2 * 8);

#define STAGE(off) do { \
        cp_async16(aD + (off), aS); cp_async16(aD + (off) + 16, aS + 8); \
        cp_async16(bD + (off), bS); cp_async16(bD + (off) + 16, bS + 8); \
        cp_commit(); aS += 32; bS += 32 * LL; } while (0)

    int lm = lane & 15, lh = lane >> 4;
    uint32_t aAddrA = smem_u32(smh + (wm * 16 + lm) * AP + lh * 8);
    uint32_t aAddrB = aAddrA + 64 * AP * 2;
    uint32_t bAddr  = smem_u32(smh + A_H + lm * BP + wn * 64 + lh * 8);

#define COMPUTE(off) do { \
        _Pragma("unroll") \
        for (int s = 0; s < 2; s++) { \
            uint32_t aa[4], ab[4]; \
            LDM_X4(aa[0], aa[1], aa[2], aa[3], aAddrA + (off) + s * 32); \
            LDM_X4(ab[0], ab[1], ab[2], ab[3], aAddrB + (off) + s * 32); \
            _Pragma("unroll") \
            for (int p = 0; p < 4; p++) { \
                uint32_t b0, b1, b2, b3; \
                LDM_X4T(b0, b1, b2, b3, bAddr + (off) + s * (16 * BP * 2) + p * 32); \
                mma_f16(ca[2 * p],     aa, b0, b1); \
                mma_f16(ca[2 * p + 1], aa, b2, b3); \
                mma_f16(cb[2 * p],     ab, b0, b1); \
                mma_f16(cb[2 * p + 1], ab, b2, b3); \
            } \
        } } while (0)

    // 3-stage pipeline over 32 chunks
    STAGE(0);
    STAGE(ST_B);
    uint32_t offC = 0, offS = 2 * ST_B;

#pragma unroll 1
    for (int i = 0; i < 32; i++) {
        if (i < 31) cp_wait1(); else cp_wait0();
        __syncthreads();
        if (i < 30) STAGE(offS);
        COMPUTE(offC);
        offC += ST_B; if (offC == 3 * ST_B) offC = 0;
        offS += ST_B; if (offS == 3 * ST_B) offS = 0;
    }

    // epilogue: bias + GLU
    int r = lane >> 2;
    int c2 = (lane & 3) << 1;
    int h = hb * 64 + wm * 16 + r;
    float ba0 = bias[h],     bb0 = bias[h + HH];
    float ba8 = bias[h + 8], bb8 = bias[h + 8 + HH];
    size_t ob0 = ((size_t)b * HH + h) * LL;
    size_t ob8 = ob0 + (size_t)8 * LL;
#pragma unroll
    for (int t = 0; t < 8; t++) {
        int ll = lblk * 128 + wn * 64 + t * 8 + c2;
        float av, bv;
        float2 w0, w8;
        av = ca[t][0] + ba0; bv = cb[t][0] + bb0;
        w0.x = av * (1.0f / (1.0f + expf(-bv)));
        av = ca[t][1] + ba0; bv = cb[t][1] + bb0;
        w0.y = av * (1.0f / (1.0f + expf(-bv)));
        av = ca[t][2] + ba8; bv = cb[t][2] + bb8;
        w8.x = av * (1.0f / (1.0f + expf(-bv)));
        av = ca[t][3] + ba8; bv = cb[t][3] + bb8;
        w8.y = av * (1.0f / (1.0f + expf(-bv)));
        *(float2*)&out[ob0 + ll] = w0;
        *(float2*)&out[ob8 + ll] = w8;
    }
}

// ---------------------------------------------------------------------------
extern "C" void kernel_launch(void* const* d_in, const int* in_sizes, int n_in,
                              void* d_out, int out_size) {
    const float* x          = (const float*)d_in[0];
    const float* log_dt     = (const float*)d_in[1];
    const float* A_real_log = (const float*)d_in[2];
    const float* A_imag     = (const float*)d_in[3];
    const float* C_re       = (const float*)d_in[4];
    const float* C_im       = (const float*)d_in[5];
    const float* D          = (const float*)d_in[6];
    const float* W_out      = (const float*)d_in[7];
    const float* b_out      = (const float*)d_in[8];
    float* out = (float*)d_out;

    cudaFuncSetAttribute(gemm_glu_kernel, cudaFuncAttributeMaxDynamicSharedMemorySize,
                         GEMM_SMEM_BYTES);

    k_kernel<<<HH, 256>>>(log_dt, A_real_log, A_imag, C_re, C_im);
    wprep_kernel<<<(2 * HH * HH) / 1024, 256>>>(W_out);
    convgemm_kernel<<<dim3(2, HH), 256>>>(x, D);
    gemm_glu_kernel<<<dim3(2, 16, BB), 256, GEMM_SMEM_BYTES>>>(b_out, out);
}

// round 17
// speedup vs baseline: 1.1758x; 1.0143x over previous
#include <cuda_runtime.h>
#include <cuda_fp16.h>
#include <cstdint>

#define BB 128
#define HH 1024
#define LL 256
#define NN 64

// Scratch (device globals: no allocations allowed)
__device__ float  g_k[HH * LL];                       // 1 MB : S4D conv kernel (H,L) fp32
__device__ __half g_Wh[2 * HH * HH];                  // 4 MB : W_out fp16
__device__ __half g_yh[(size_t)BB * HH * LL];         // 64 MB: post-gelu activations fp16 [b][h][l]

// ---------------------------------------------------------------------------
// helpers
// ---------------------------------------------------------------------------
__device__ __forceinline__ float gelu_tanh(float v) {
    float t = tanhf(0.7978845608028654f * (v + 0.044715f * v * v * v));
    return 0.5f * v * (1.0f + t);
}
__device__ __forceinline__ uint32_t smem_u32(const void* p) {
    return (uint32_t)__cvta_generic_to_shared(p);
}
__device__ __forceinline__ void cp_async16(uint32_t dst, const void* src) {
    asm volatile("cp.async.cg.shared.global [%0], [%1], 16;\n" :: "r"(dst), "l"(src));
}
__device__ __forceinline__ void cp_commit() { asm volatile("cp.async.commit_group;\n"); }
__device__ __forceinline__ void cp_wait0() { asm volatile("cp.async.wait_group 0;\n"); }
__device__ __forceinline__ void cp_wait1() { asm volatile("cp.async.wait_group 1;\n"); }

__device__ __forceinline__ void mma_f16(float c[4], const uint32_t a[4],
                                        uint32_t b0, uint32_t b1) {
    asm volatile(
        "mma.sync.aligned.m16n8k16.row.col.f32.f16.f16.f32 "
        "{%0,%1,%2,%3}, {%4,%5,%6,%7}, {%8,%9}, {%0,%1,%2,%3};"
        : "+f"(c[0]), "+f"(c[1]), "+f"(c[2]), "+f"(c[3])
        : "r"(a[0]), "r"(a[1]), "r"(a[2]), "r"(a[3]), "r"(b0), "r"(b1));
}

#define LDM_X4(r0, r1, r2, r3, addr) \
    asm volatile("ldmatrix.sync.aligned.m8n8.x4.shared.b16 {%0,%1,%2,%3}, [%4];" \
                 : "=r"(r0), "=r"(r1), "=r"(r2), "=r"(r3) : "r"(addr))
#define LDM_X4T(r0, r1, r2, r3, addr) \
    asm volatile("ldmatrix.sync.aligned.m8n8.x4.trans.shared.b16 {%0,%1,%2,%3}, [%4];" \
                 : "=r"(r0), "=r"(r1), "=r"(r2), "=r"(r3) : "r"(addr))

// ---------------------------------------------------------------------------
// Kernel 1: S4D kernel materialization (fp32 k)
// ---------------------------------------------------------------------------
__global__ __launch_bounds__(256) void k_kernel(
    const float* __restrict__ log_dt, const float* __restrict__ A_real_log,
    const float* __restrict__ A_imag, const float* __restrict__ C_re,
    const float* __restrict__ C_im) {
    int h = blockIdx.x;
    __shared__ float sCr[NN], sCi[NN], sAr[NN], sAi[NN];
    int tid = threadIdx.x;
    if (tid < NN) {
        float dt = expf(log_dt[h]);
        float Ar = -expf(A_real_log[h * NN + tid]);
        float Ai = A_imag[h * NN + tid];
        float dAr = Ar * dt, dAi = Ai * dt;
        float er = expf(dAr), sv, cv;
        sincosf(dAi, &sv, &cv);
        float Exr = er * cv - 1.0f;
        float Exi = er * sv;
        float cr = C_re[h * NN + tid], ci = C_im[h * NN + tid];
        float nr = cr * Exr - ci * Exi;
        float ni = cr * Exi + ci * Exr;
        float den = 1.0f / (Ar * Ar + Ai * Ai);
        sCr[tid] = (nr * Ar + ni * Ai) * den;
        sCi[tid] = (ni * Ar - nr * Ai) * den;
        sAr[tid] = dAr;
        sAi[tid] = dAi;
    }
    __syncthreads();
    float l = (float)tid;
    float acc = 0.0f;
#pragma unroll 4
    for (int n = 0; n < NN; n++) {
        float mag = expf(sAr[n] * l);
        float sv, cv;
        sincosf(sAi[n] * l, &sv, &cv);
        acc += sCr[n] * (mag * cv) - sCi[n] * (mag * sv);
    }
    g_k[h * LL + tid] = 2.0f * acc;
}

// ---------------------------------------------------------------------------
// Kernel 2: fp16-cast W (row-major)
// ---------------------------------------------------------------------------
__global__ __launch_bounds__(256) void wprep_kernel(const float* __restrict__ W) {
    int i = (blockIdx.x * 256 + threadIdx.x) * 4;
    if (i >= 2 * HH * HH) return;
    float4 v = *(const float4*)&W[i];
    union { __half2 h[2]; uint2 u; } c;
    c.h[0] = __floats2half2_rn(v.x, v.y);
    c.h[1] = __floats2half2_rn(v.z, v.w);
    *(uint2*)&g_Wh[i] = c.u;
}

// ---------------------------------------------------------------------------
// Kernel 3: conv as per-head Toeplitz GEMM (tensor cores).
// Y[b][l] = sum_s X[b][s] * T[s][l],  T[s][l] = k_h[l-s] (l>=s else 0)
// Block = (mb in 0..1, head h): M=64 batches, N=256 l, K=256 s in 16 chunks.
// 8 warps = 2(m) x 4(n). INTERLEAVED causal n-assignment: warp wn owns
// n16-tiles {wn, wn+4, wn+8, wn+12} (cols q*64+wn*16), so causal work is
// balanced across warps (max 40 tile-chunks vs 58 contiguous).
// GEN_T uses a zero-padded kernel row khp[512] -> predicate-free copies,
// and an exact 16-col write guard (l0g >= k0).
// X staged directly from fp32 x (LDG->cvt->STS, prefetch-overlapped).
// Epilogue: + D*x (fp32 read), gelu, fp16 store. mma rows are BATCHES
// (stride HH*LL); m16 sub-tiles at row offsets +0/+16.
// ---------------------------------------------------------------------------
#define XP 24          // X tile pitch (halfs)
#define TP 264         // T tile pitch (halfs)

__global__ __launch_bounds__(256) void convgemm_kernel(const float* __restrict__ x,
                                                       const float* __restrict__ D) {
    __shared__ __half khp[512];                         // [0..255]=0, [256..511]=k_h
    __shared__ __align__(16) __half Xs[2][64 * XP];     // 6144 B
    __shared__ __align__(16) __half Ts[2][16 * TP];     // 16896 B

    int mb = blockIdx.x;            // 0..1 (64 batches each)
    int h  = blockIdx.y;
    int tid = threadIdx.x;
    int lane = tid & 31;
    int wid = tid >> 5;
    int wm = wid & 1;               // m: 32 rows
    int wn = wid >> 1;              // n: interleaved tiles wn, wn+4, wn+8, wn+12

    // zero-padded kernel row -> fp16 smem
    khp[tid] = __half(0.0f);
    khp[256 + tid] = __float2half(g_k[(size_t)h * LL + tid]);

    float acc[2][8][4];
#pragma unroll
    for (int mi = 0; mi < 2; mi++)
#pragma unroll
        for (int t = 0; t < 8; t++)
#pragma unroll
            for (int r = 0; r < 4; r++) acc[mi][t][r] = 0.0f;

    // X staging: threads 0..127 -> (row xr, 8-half segment xseg), from fp32 x
    int xr = tid >> 1, xseg = (tid & 1) * 8;
    const float* xF = x + ((size_t)(mb * 64 + xr) * HH + h) * LL + xseg;   // += 16/chunk
    __half* xDst[2] = { &Xs[0][xr * XP + xseg], &Xs[1][xr * XP + xseg] };

    // T generation mapping: si = tid>>4 (s within chunk), l0g = (tid&15)*16
    int si = tid >> 4;
    int l0g = (tid & 15) * 16;

    // fragment addresses
    int lm = lane & 15, lh = lane >> 4;
    uint32_t xAddr[2] = { smem_u32(&Xs[0][(wm * 32 + lm) * XP + lh * 8]),
                          smem_u32(&Xs[1][(wm * 32 + lm) * XP + lh * 8]) };
    uint32_t tAddr[2] = { smem_u32(&Ts[0][lm * TP + wn * 16 + lh * 8]),
                          smem_u32(&Ts[1][lm * TP + wn * 16 + lh * 8]) };

#define GEN_T(buf, k0) do { \
        if (l0g >= (k0)) { \
            int base = 256 + l0g - ((k0) + si); \
            _Pragma("unroll") \
            for (int j = 0; j < 8; j++) { \
                *(__half2*)&Ts[buf][si * TP + l0g + 2 * j] = \
                    __halves2half2(khp[base + 2 * j], khp[base + 2 * j + 1]); \
            } \
        } } while (0)

#define LOAD_X_REGS(v0, v1) do { \
        if (tid < 128) { v0 = *(const float4*)xF; v1 = *(const float4*)(xF + 4); xF += 16; } \
        } while (0)

#define STS_X(buf, v0, v1) do { \
        if (tid < 128) { \
            union { __half hv[8]; uint4 u; } cvt; \
            *(__half2*)&cvt.hv[0] = __floats2half2_rn(v0.x, v0.y); \
            *(__half2*)&cvt.hv[2] = __floats2half2_rn(v0.z, v0.w); \
            *(__half2*)&cvt.hv[4] = __floats2half2_rn(v1.x, v1.y); \
            *(__half2*)&cvt.hv[6] = __floats2half2_rn(v1.z, v1.w); \
            *(uint4*)xDst[buf] = cvt.u; \
        } } while (0)

    // c = chunk index (k0 = c*16). Warp wn active for tile q iff q*4+wn >= c.
#define CONV_COMPUTE(buf, c) do { \
        if (12 + wn >= (c)) { \
            uint32_t aa0[4], aa1[4]; \
            LDM_X4(aa0[0], aa0[1], aa0[2], aa0[3], xAddr[buf]); \
            LDM_X4(aa1[0], aa1[1], aa1[2], aa1[3], xAddr[buf] + 16 * XP * 2); \
            _Pragma("unroll") \
            for (int q = 0; q < 4; q++) { \
                if (q * 4 + wn >= (c)) { \
                    uint32_t b0, b1, b2, b3; \
                    LDM_X4T(b0, b1, b2, b3, tAddr[buf] + q * 128); \
                    mma_f16(acc[0][2 * q],     aa0, b0, b1); \
                    mma_f16(acc[0][2 * q + 1], aa0, b2, b3); \
                    mma_f16(acc[1][2 * q],     aa1, b0, b1); \
                    mma_f16(acc[1][2 * q + 1], aa1, b2, b3); \
                } \
            } \
        } } while (0)

    // prologue: chunk 0 -> buf0 (barrier first: GEN_T reads khp written above)
    __syncthreads();
    {
        float4 v0, v1;
        LOAD_X_REGS(v0, v1);
        GEN_T(0, 0);
        STS_X(0, v0, v1);
    }
    __syncthreads();

#pragma unroll 1
    for (int c = 0; c < 16; c++) {
        int cur = c & 1, nxt = cur ^ 1;
        float4 v0, v1;
        if (c < 15) {
            LOAD_X_REGS(v0, v1);        // LDG latency overlaps GEN_T + compute
            GEN_T(nxt, (c + 1) * 16);
        }
        CONV_COMPUTE(cur, c);
        if (c < 15) STS_X(nxt, v0, v1);
        __syncthreads();
    }

    // epilogue: + D*x (fp32), gelu, store fp16.
    // acc[mi][2q+e] -> cols q*64 + wn*16 + e*8 + c2; batch stride = HH*LL.
    float Dv = D[h];
    int r = lane >> 2;
    int c2 = (lane & 3) << 1;
    const size_t BSTRIDE8 = (size_t)8 * HH * LL;
#pragma unroll
    for (int mi = 0; mi < 2; mi++) {
        int row0 = mb * 64 + wm * 32 + mi * 16 + r;      // batch index
#pragma unroll
        for (int q = 0; q < 4; q++) {
#pragma unroll
            for (int e = 0; e < 2; e++) {
                int l = q * 64 + wn * 16 + e * 8 + c2;
                int t = 2 * q + e;
                size_t a0 = ((size_t)row0 * HH + h) * LL + l;
                size_t a8 = a0 + BSTRIDE8;               // batch row0+8
                float2 x0 = *(const float2*)&x[a0];
                float2 x8 = *(const float2*)&x[a8];
                float y0 = gelu_tanh(acc[mi][t][0] + Dv * x0.x);
                float y1 = gelu_tanh(acc[mi][t][1] + Dv * x0.y);
                float y2 = gelu_tanh(acc[mi][t][2] + Dv * x8.x);
                float y3 = gelu_tanh(acc[mi][t][3] + Dv * x8.y);
                *(__half2*)&g_yh[a0] = __floats2half2_rn(y0, y1);
                *(__half2*)&g_yh[a8] = __floats2half2_rn(y2, y3);
            }
        }
    }
}

// ---------------------------------------------------------------------------
// Kernel 4: fp16 GEMM + GLU (mma.sync m16n8k16 + ldmatrix), 3-stage cp.async
// pipeline with wait_group 1 (one barrier per k32 chunk). R10/R15-proven.
// Block: 64 h-out (both GLU halves) x 128 l; 8 warps = 4(m) x 2(n).
// ---------------------------------------------------------------------------
#define AP 40
#define BP 136
#define A_H (128 * AP)                 // 5120 halfs
#define B_H (32 * BP)                  // 4352 halfs
#define ST_H (A_H + B_H)               // 9472 halfs
#define ST_B (ST_H * 2)                // 18944 B / stage
#define GEMM_SMEM_BYTES (3 * ST_B)     // 56832 B

__global__ __launch_bounds__(256, 2) void gemm_glu_kernel(const float* __restrict__ bias,
                                                          float* __restrict__ out) {
    extern __shared__ __half smh[];

    int lblk = blockIdx.x;
    int hb   = blockIdx.y;
    int b    = blockIdx.z;
    int tid = threadIdx.x;
    int lane = tid & 31;
    int wid = tid >> 5;
    int wm = wid & 3;
    int wn = wid >> 2;

    float ca[8][4], cb[8][4];
#pragma unroll
    for (int t = 0; t < 8; t++)
#pragma unroll
        for (int r = 0; r < 4; r++) { ca[t][r] = 0.0f; cb[t][r] = 0.0f; }

    // staging descriptors
    int arow = tid >> 1, aseg2 = (tid & 1) * 2;
    int wrow = (arow < 64) ? (hb * 64 + arow) : (960 + hb * 64 + arow);
    const __half* aS = g_Wh + (size_t)wrow * HH + aseg2 * 8;
    uint32_t aD = smem_u32(smh + arow * AP + aseg2 * 8);

    int brow = tid >> 3, bs2 = (tid & 7) * 2;
    const __half* bS = g_yh + (size_t)b * HH * LL + (size_t)brow * LL + lblk * 128 + bs2 * 8;
    uint32_t bD = smem_u32(smh + A_H + brow * BP + bs2 * 8);

#define STAGE(off) do { \
        cp_async16(aD + (off), aS); cp_async16(aD + (off) + 16, aS + 8); \
        cp_async16(bD + (off), bS); cp_async16(bD + (off) + 16, bS + 8); \
        cp_commit(); aS += 32; bS += 32 * LL; } while (0)

    int lm = lane & 15, lh = lane >> 4;
    uint32_t aAddrA = smem_u32(smh + (wm * 16 + lm) * AP + lh * 8);
    uint32_t aAddrB = aAddrA + 64 * AP * 2;
    uint32_t bAddr  = smem_u32(smh + A_H + lm * BP + wn * 64 + lh * 8);

#define COMPUTE(off) do { \
        _Pragma("unroll") \
        for (int s = 0; s < 2; s++) { \
            uint32_t aa[4], ab[4]; \
            LDM_X4(aa[0], aa[1], aa[2], aa[3], aAddrA + (off) + s * 32); \
            LDM_X4(ab[0], ab[1], ab[2], ab[3], aAddrB + (off) + s * 32); \
            _Pragma("unroll") \
            for (int p = 0; p < 4; p++) { \
                uint32_t b0, b1, b2, b3; \
                LDM_X4T(b0, b1, b2, b3, bAddr + (off) + s * (16 * BP * 2) + p * 32); \
                mma_f16(ca[2 * p],     aa, b0, b1); \
                mma_f16(ca[2 * p + 1], aa, b2, b3); \
                mma_f16(cb[2 * p],     ab, b0, b1); \
                mma_f16(cb[2 * p + 1], ab, b2, b3); \
            } \
        } } while (0)

    // 3-stage pipeline over 32 chunks
    STAGE(0);
    STAGE(ST_B);
    uint32_t offC = 0, offS = 2 * ST_B;

#pragma unroll 1
    for (int i = 0; i < 32; i++) {
        if (i < 31) cp_wait1(); else cp_wait0();
        __syncthreads();
        if (i < 30) STAGE(offS);
        COMPUTE(offC);
        offC += ST_B; if (offC == 3 * ST_B) offC = 0;
        offS += ST_B; if (offS == 3 * ST_B) offS = 0;
    }

    // epilogue: bias + GLU
    int r = lane >> 2;
    int c2 = (lane & 3) << 1;
    int h = hb * 64 + wm * 16 + r;
    float ba0 = bias[h],     bb0 = bias[h + HH];
    float ba8 = bias[h + 8], bb8 = bias[h + 8 + HH];
    size_t ob0 = ((size_t)b * HH + h) * LL;
    size_t ob8 = ob0 + (size_t)8 * LL;
#pragma unroll
    for (int t = 0; t < 8; t++) {
        int ll = lblk * 128 + wn * 64 + t * 8 + c2;
        float av, bv;
        float2 w0, w8;
        av = ca[t][0] + ba0; bv = cb[t][0] + bb0;
        w0.x = av * (1.0f / (1.0f + expf(-bv)));
        av = ca[t][1] + ba0; bv = cb[t][1] + bb0;
        w0.y = av * (1.0f / (1.0f + expf(-bv)));
        av = ca[t][2] + ba8; bv = cb[t][2] + bb8;
        w8.x = av * (1.0f / (1.0f + expf(-bv)));
        av = ca[t][3] + ba8; bv = cb[t][3] + bb8;
        w8.y = av * (1.0f / (1.0f + expf(-bv)));
        *(float2*)&out[ob0 + ll] = w0;
        *(float2*)&out[ob8 + ll] = w8;
    }
}

// ---------------------------------------------------------------------------
extern "C" void kernel_launch(void* const* d_in, const int* in_sizes, int n_in,
                              void* d_out, int out_size) {
    const float* x          = (const float*)d_in[0];
    const float* log_dt     = (const float*)d_in[1];
    const float* A_real_log = (const float*)d_in[2];
    const float* A_imag     = (const float*)d_in[3];
    const float* C_re       = (const float*)d_in[4];
    const float* C_im       = (const float*)d_in[5];
    const float* D          = (const float*)d_in[6];
    const float* W_out      = (const float*)d_in[7];
    const float* b_out      = (const float*)d_in[8];
    float* out = (float*)d_out;

    cudaFuncSetAttribute(gemm_glu_kernel, cudaFuncAttributeMaxDynamicSharedMemorySize,
                         GEMM_SMEM_BYTES);

    k_kernel<<<HH, 256>>>(log_dt, A_real_log, A_imag, C_re, C_im);
    wprep_kernel<<<(2 * HH * HH) / 1024, 256>>>(W_out);
    convgemm_kernel<<<dim3(2, HH), 256>>>(x, D);
    gemm_glu_kernel<<<dim3(2, 16, BB), 256, GEMM_SMEM_BYTES>>>(b_out, out);
}